// round 1
// baseline (speedup 1.0000x reference)
#include <cuda_runtime.h>
#include <cuda_bf16.h>
#include <math_constants.h>

// ---------------- f32x2 helpers (Blackwell packed fp32) ----------------
typedef unsigned long long ull;

__device__ __forceinline__ ull pk2(float lo, float hi) {
    ull r;
    asm("mov.b64 %0, {%1, %2};" : "=l"(r) : "f"(lo), "f"(hi));
    return r;
}
__device__ __forceinline__ void unpk2(ull v, float& lo, float& hi) {
    asm("mov.b64 {%0, %1}, %2;" : "=f"(lo), "=f"(hi) : "l"(v));
}
__device__ __forceinline__ void fma2(ull& acc, ull a, ull b) {
    asm("fma.rn.f32x2 %0, %1, %2, %0;" : "+l"(acc) : "l"(a), "l"(b));
}

// ---------------- scratch buffers (no allocation allowed) ----------------
__device__ __align__(16) float g_A1[2048 * 32 * 12 * 12];   // post conv1 block
__device__ __align__(16) float g_A2[2048 * 1024];           // post conv2 block (flattened)
__device__ __align__(16) float g_F1[2048 * 512];            // fc1 pre-ternarize
__device__ __align__(16) float g_W2T[800 * 64];             // conv2 weights transposed [k][co]

#define BN_INV 0.9999950000374997f   // 1/sqrt(1+1e-5), rounded to f32

// ---------------- block reduction (NW warps) ----------------
template <int NW>
__device__ __forceinline__ float blockReduce(float v) {
    __shared__ float r[NW];
    #pragma unroll
    for (int o = 16; o > 0; o >>= 1) v += __shfl_xor_sync(0xFFFFFFFFu, v, o);
    int wid = threadIdx.x >> 5, lane = threadIdx.x & 31;
    __syncthreads();                 // protect r from previous use
    if (lane == 0) r[wid] = v;
    __syncthreads();
    float t = 0.f;
    #pragma unroll
    for (int i = 0; i < NW; i++) t += r[i];
    return t;
}

__device__ __forceinline__ float tern_val(float v, float delta, float alpha) {
    return (v > delta) ? alpha : ((v < -delta) ? -alpha : 0.f);
}

// ---------------- kernel 0: transpose conv2 weights ----------------
__global__ void k_wt(const float* __restrict__ w2) {
    int i = blockIdx.x * 256 + threadIdx.x;
    if (i < 64 * 800) {
        int co = i / 800, k = i % 800;
        g_W2T[k * 64 + co] = w2[i];
    }
}

// ---------------- kernel 1: conv1 + ternarize + BN + pool + ReLU ----------------
// one block per image; conv1 output (18432 floats) stays in smem
__global__ void __launch_bounds__(256) k_conv1(
    const float* __restrict__ x, const float* __restrict__ w,
    const float* __restrict__ bias, const float* __restrict__ bng,
    const float* __restrict__ bnb)
{
    extern __shared__ float sm[];
    float* sx  = sm;           // 784
    float* sw  = sm + 784;     // 800
    float* sb  = sw + 800;     // 32
    float* sc1 = sb + 32;      // 18432
    __shared__ float sscale[32], sbeta[32];

    int b = blockIdx.x, tid = threadIdx.x;
    const float* xb = x + b * 784;
    for (int i = tid; i < 784; i += 256) sx[i] = xb[i];
    for (int i = tid; i < 800; i += 256) sw[i] = w[i];
    if (tid < 32) {
        sb[tid]     = bias[tid];
        sscale[tid] = bng[tid] * BN_INV;
        sbeta[tid]  = bnb[tid];
    }
    __syncthreads();

    // conv1: 32ch x 24x24, packed pairs along x (9216 pair-units)
    float asum = 0.f;
    for (int u = tid; u < 9216; u += 256) {
        int c = u / 288, pp = u % 288;
        int oy = pp / 12, ox = (pp % 12) * 2;
        float bv = sb[c];
        ull acc = pk2(bv, bv);
        const float* wr = sw + c * 25;
        #pragma unroll
        for (int ky = 0; ky < 5; ky++) {
            const float* xr = sx + (oy + ky) * 28 + ox;
            #pragma unroll
            for (int kx = 0; kx < 5; kx++) {
                float wv = wr[ky * 5 + kx];
                fma2(acc, pk2(xr[kx], xr[kx + 1]), pk2(wv, wv));
            }
        }
        float lo, hi; unpk2(acc, lo, hi);
        int base = c * 576 + oy * 24 + ox;
        sc1[base] = lo; sc1[base + 1] = hi;
        asum += fabsf(lo) + fabsf(hi);
    }

    float tot = blockReduce<8>(asum);          // also fences sc1 writes
    float delta = 0.7f * tot / 18432.0f;

    float ms = 0.f, mc = 0.f;
    for (int u = tid; u < 18432; u += 256) {
        float a = fabsf(sc1[u]);
        if (a > delta) { ms += a; mc += 1.f; }
    }
    ms = blockReduce<8>(ms);
    mc = blockReduce<8>(mc);
    float alpha = ms / mc;

    // ternarize + BN + maxpool2 + ReLU -> [32,12,12]
    for (int u = tid; u < 4608; u += 256) {
        int c = u / 144, p = u % 144;
        int py = p / 12, px = p % 12;
        const float* q = sc1 + c * 576 + (2 * py) * 24 + 2 * px;
        float sc = sscale[c], bt = sbeta[c];
        float m = -CUDART_INF_F;
        float v;
        v = q[0];  m = fmaxf(m, fmaf(tern_val(v, delta, alpha), sc, bt));
        v = q[1];  m = fmaxf(m, fmaf(tern_val(v, delta, alpha), sc, bt));
        v = q[24]; m = fmaxf(m, fmaf(tern_val(v, delta, alpha), sc, bt));
        v = q[25]; m = fmaxf(m, fmaf(tern_val(v, delta, alpha), sc, bt));
        g_A1[b * 4608 + u] = fmaxf(m, 0.f);
    }
}

// ---------------- kernel 2: conv2 + ternarize + BN + pool + ReLU ----------------
// one block per image. 8 warps = 8 co-groups (8 out-channels each),
// 32 lanes = 32 position-pairs. per-k: 2 LDS + 2 uniform LDG.128 + 8 FFMA2.
__global__ void __launch_bounds__(256) k_conv2(
    const float* __restrict__ bias, const float* __restrict__ bng,
    const float* __restrict__ bnb)
{
    __shared__ float sin_[4608];
    __shared__ float sout[4096];
    __shared__ int   offs[800];
    __shared__ float sscale[64], sbeta[64], sb2[64];

    int b = blockIdx.x, tid = threadIdx.x;
    for (int i = tid; i < 4608; i += 256) sin_[i] = g_A1[b * 4608 + i];
    for (int k = tid; k < 800; k += 256) {
        int ci = k / 25, r = k % 25;
        offs[k] = ci * 144 + (r / 5) * 12 + (r % 5);
    }
    if (tid < 64) {
        sb2[tid]    = bias[tid];
        sscale[tid] = bng[tid] * BN_INV;
        sbeta[tid]  = bnb[tid];
    }
    __syncthreads();

    int w = tid >> 5, l = tid & 31;
    int p0 = 2 * l;
    int py = p0 >> 3, px = p0 & 7;
    int inbase = py * 12 + px;
    int cobase = w * 8;

    ull acc[8];
    #pragma unroll
    for (int j = 0; j < 8; j++) {
        float bv = sb2[cobase + j];
        acc[j] = pk2(bv, bv);
    }

    const float4* wt = ((const float4*)g_W2T) + w * 2;
    #pragma unroll 4
    for (int k = 0; k < 800; k++) {
        int o = inbase + offs[k];
        ull iv = pk2(sin_[o], sin_[o + 1]);
        float4 wa = wt[k * 16];
        float4 wb = wt[k * 16 + 1];
        fma2(acc[0], iv, pk2(wa.x, wa.x));
        fma2(acc[1], iv, pk2(wa.y, wa.y));
        fma2(acc[2], iv, pk2(wa.z, wa.z));
        fma2(acc[3], iv, pk2(wa.w, wa.w));
        fma2(acc[4], iv, pk2(wb.x, wb.x));
        fma2(acc[5], iv, pk2(wb.y, wb.y));
        fma2(acc[6], iv, pk2(wb.z, wb.z));
        fma2(acc[7], iv, pk2(wb.w, wb.w));
    }

    float asum = 0.f;
    #pragma unroll
    for (int j = 0; j < 8; j++) {
        float lo, hi; unpk2(acc[j], lo, hi);
        int co = cobase + j;
        sout[co * 64 + p0] = lo;
        sout[co * 64 + p0 + 1] = hi;
        asum += fabsf(lo) + fabsf(hi);
    }

    float tot = blockReduce<8>(asum);
    float delta = 0.7f * tot / 4096.0f;

    float ms = 0.f, mc = 0.f;
    #pragma unroll
    for (int j = 0; j < 8; j++) {
        float lo, hi; unpk2(acc[j], lo, hi);
        float a = fabsf(lo); if (a > delta) { ms += a; mc += 1.f; }
        a = fabsf(hi);       if (a > delta) { ms += a; mc += 1.f; }
    }
    ms = blockReduce<8>(ms);
    mc = blockReduce<8>(mc);
    float alpha = ms / mc;

    // ternarize + BN + maxpool2 + ReLU -> flattened [64*4*4]
    for (int u = tid; u < 1024; u += 256) {
        int c = u >> 4, p = u & 15;
        int py2 = p >> 2, px2 = p & 3;
        const float* q = sout + c * 64 + (2 * py2) * 8 + 2 * px2;
        float sc = sscale[c], bt = sbeta[c];
        float m = -CUDART_INF_F;
        float v;
        v = q[0]; m = fmaxf(m, fmaf(tern_val(v, delta, alpha), sc, bt));
        v = q[1]; m = fmaxf(m, fmaf(tern_val(v, delta, alpha), sc, bt));
        v = q[8]; m = fmaxf(m, fmaf(tern_val(v, delta, alpha), sc, bt));
        v = q[9]; m = fmaxf(m, fmaf(tern_val(v, delta, alpha), sc, bt));
        g_A2[b * 1024 + u] = fmaxf(m, 0.f);
    }
}

// ---------------- kernel 3: fc1 GEMM  F1 = A2 @ W1^T + b1 ----------------
#define FBM 64
#define FBN 64
#define FBK 32
__global__ void __launch_bounds__(256) k_fc1(
    const float* __restrict__ W, const float* __restrict__ bias)
{
    __shared__ __align__(16) float As[FBK][FBM + 4];
    __shared__ __align__(16) float Bs[FBK][FBN + 4];

    int bm = blockIdx.y * FBM, bn = blockIdx.x * FBN;
    int tid = threadIdx.x;
    int tx = tid & 15, ty = tid >> 4;

    ull acc[4][2];
    #pragma unroll
    for (int i = 0; i < 4; i++) { acc[i][0] = 0ull; acc[i][1] = 0ull; }

    for (int k0 = 0; k0 < 1024; k0 += FBK) {
        #pragma unroll
        for (int i = 0; i < 2; i++) {
            int f = tid * 2 + i;
            int row = f >> 3, kc = f & 7;
            float4 va = *(const float4*)(g_A2 + (bm + row) * 1024 + k0 + kc * 4);
            As[kc * 4 + 0][row] = va.x;
            As[kc * 4 + 1][row] = va.y;
            As[kc * 4 + 2][row] = va.z;
            As[kc * 4 + 3][row] = va.w;
            float4 vb = *(const float4*)(W + (bn + row) * 1024 + k0 + kc * 4);
            Bs[kc * 4 + 0][row] = vb.x;
            Bs[kc * 4 + 1][row] = vb.y;
            Bs[kc * 4 + 2][row] = vb.z;
            Bs[kc * 4 + 3][row] = vb.w;
        }
        __syncthreads();
        #pragma unroll
        for (int kk = 0; kk < FBK; kk++) {
            float4 a4 = *(const float4*)&As[kk][ty * 4];
            float4 b4 = *(const float4*)&Bs[kk][tx * 4];
            ull b01 = pk2(b4.x, b4.y), b23 = pk2(b4.z, b4.w);
            fma2(acc[0][0], pk2(a4.x, a4.x), b01); fma2(acc[0][1], pk2(a4.x, a4.x), b23);
            fma2(acc[1][0], pk2(a4.y, a4.y), b01); fma2(acc[1][1], pk2(a4.y, a4.y), b23);
            fma2(acc[2][0], pk2(a4.z, a4.z), b01); fma2(acc[2][1], pk2(a4.z, a4.z), b23);
            fma2(acc[3][0], pk2(a4.w, a4.w), b01); fma2(acc[3][1], pk2(a4.w, a4.w), b23);
        }
        __syncthreads();
    }

    float bl0 = bias[bn + tx * 4 + 0];
    float bl1 = bias[bn + tx * 4 + 1];
    float bl2 = bias[bn + tx * 4 + 2];
    float bl3 = bias[bn + tx * 4 + 3];
    #pragma unroll
    for (int i = 0; i < 4; i++) {
        int m = bm + ty * 4 + i;
        float lo, hi;
        unpk2(acc[i][0], lo, hi);
        g_F1[m * 512 + bn + tx * 4 + 0] = lo + bl0;
        g_F1[m * 512 + bn + tx * 4 + 1] = hi + bl1;
        unpk2(acc[i][1], lo, hi);
        g_F1[m * 512 + bn + tx * 4 + 2] = lo + bl2;
        g_F1[m * 512 + bn + tx * 4 + 3] = hi + bl3;
    }
}

// ---------------- kernel 4: per-row ternarize+ReLU -> fc2 -> ternarize ----------------
__global__ void __launch_bounds__(128) k_head(
    const float* __restrict__ W2, const float* __restrict__ b2,
    float* __restrict__ out)
{
    __shared__ float sh[512];
    __shared__ float so[10];

    int b = blockIdx.x, tid = threadIdx.x;
    float v[4];
    float asum = 0.f;
    #pragma unroll
    for (int i = 0; i < 4; i++) {
        v[i] = g_F1[b * 512 + tid + i * 128];
        asum += fabsf(v[i]);
    }
    float tot = blockReduce<4>(asum);
    float delta = 0.7f * tot / 512.0f;

    float ms = 0.f, mc = 0.f;
    #pragma unroll
    for (int i = 0; i < 4; i++) {
        float a = fabsf(v[i]);
        if (a > delta) { ms += a; mc += 1.f; }
    }
    ms = blockReduce<4>(ms);
    mc = blockReduce<4>(mc);
    float alpha = ms / mc;

    #pragma unroll
    for (int i = 0; i < 4; i++)
        sh[tid + i * 128] = (v[i] > delta) ? alpha : 0.f;   // relu(ternarize)
    __syncthreads();

    if (tid < 32) {
        for (int n = 0; n < 10; n++) {
            float s = 0.f;
            for (int j = tid; j < 512; j += 32)
                s += sh[j] * W2[n * 512 + j];
            #pragma unroll
            for (int o = 16; o > 0; o >>= 1) s += __shfl_xor_sync(0xFFFFFFFFu, s, o);
            if (tid == 0) so[n] = s + b2[n];
        }
    }
    __syncthreads();

    if (tid == 0) {
        float s = 0.f;
        #pragma unroll
        for (int n = 0; n < 10; n++) s += fabsf(so[n]);
        float d2 = 0.7f * s / 10.0f;
        float ms2 = 0.f, c2 = 0.f;
        #pragma unroll
        for (int n = 0; n < 10; n++) {
            float a = fabsf(so[n]);
            if (a > d2) { ms2 += a; c2 += 1.f; }
        }
        float a2 = ms2 / c2;
        #pragma unroll
        for (int n = 0; n < 10; n++)
            out[b * 10 + n] = tern_val(so[n], d2, a2);
    }
}

// ---------------- launch ----------------
extern "C" void kernel_launch(void* const* d_in, const int* in_sizes, int n_in,
                              void* d_out, int out_size)
{
    (void)in_sizes; (void)n_in; (void)out_size;
    const float* x       = (const float*)d_in[0];
    const float* conv1_w = (const float*)d_in[1];
    const float* conv1_b = (const float*)d_in[2];
    const float* bn1_g   = (const float*)d_in[3];
    const float* bn1_b   = (const float*)d_in[4];
    const float* conv2_w = (const float*)d_in[5];
    const float* conv2_b = (const float*)d_in[6];
    const float* bn2_g   = (const float*)d_in[7];
    const float* bn2_b   = (const float*)d_in[8];
    const float* fc1_w   = (const float*)d_in[9];
    const float* fc1_b   = (const float*)d_in[10];
    const float* fc2_w   = (const float*)d_in[11];
    const float* fc2_b   = (const float*)d_in[12];
    float* out = (float*)d_out;

    const int SMEM1 = (784 + 800 + 32 + 18432) * 4;   // 80192 B dynamic
    cudaFuncSetAttribute(k_conv1, cudaFuncAttributeMaxDynamicSharedMemorySize, SMEM1);

    k_wt<<<(64 * 800 + 255) / 256, 256>>>(conv2_w);
    k_conv1<<<2048, 256, SMEM1>>>(x, conv1_w, conv1_b, bn1_g, bn1_b);
    k_conv2<<<2048, 256>>>(conv2_b, bn2_g, bn2_b);
    k_fc1<<<dim3(512 / FBN, 2048 / FBM), 256>>>(fc1_w, fc1_b);
    k_head<<<2048, 128>>>(fc2_w, fc2_b, out);
}

// round 2
// speedup vs baseline: 1.6292x; 1.6292x over previous
#include <cuda_runtime.h>
#include <cuda_bf16.h>
#include <math_constants.h>

// ---------------- f32x2 helpers (Blackwell packed fp32) ----------------
typedef unsigned long long ull;

__device__ __forceinline__ ull pk2(float lo, float hi) {
    ull r;
    asm("mov.b64 %0, {%1, %2};" : "=l"(r) : "f"(lo), "f"(hi));
    return r;
}
__device__ __forceinline__ void unpk2(ull v, float& lo, float& hi) {
    asm("mov.b64 {%0, %1}, %2;" : "=f"(lo), "=f"(hi) : "l"(v));
}
__device__ __forceinline__ void fma2(ull& acc, ull a, ull b) {
    asm("fma.rn.f32x2 %0, %1, %2, %0;" : "+l"(acc) : "l"(a), "l"(b));
}

// ---------------- scratch buffers (no allocation allowed) ----------------
__device__ __align__(16) float g_A1[2048 * 32 * 12 * 12];   // post conv1 block
__device__ __align__(16) float g_A2[2048 * 1024];           // post conv2 block (flattened)
__device__ __align__(16) float g_F1[2048 * 512];            // fc1 pre-ternarize
__device__ __align__(16) float g_W2T[800 * 64];             // conv2 weights transposed [k][co]

#define BN_INV 0.9999950000374997f   // 1/sqrt(1+1e-5), rounded to f32

// ---------------- block reduction (NW warps) ----------------
template <int NW>
__device__ __forceinline__ float blockReduce(float v) {
    __shared__ float r[NW];
    #pragma unroll
    for (int o = 16; o > 0; o >>= 1) v += __shfl_xor_sync(0xFFFFFFFFu, v, o);
    int wid = threadIdx.x >> 5, lane = threadIdx.x & 31;
    __syncthreads();                 // protect r from previous use
    if (lane == 0) r[wid] = v;
    __syncthreads();
    float t = 0.f;
    #pragma unroll
    for (int i = 0; i < NW; i++) t += r[i];
    return t;
}

__device__ __forceinline__ float tern_val(float v, float delta, float alpha) {
    return (v > delta) ? alpha : ((v < -delta) ? -alpha : 0.f);
}

// ---------------- kernel 0: transpose conv2 weights ----------------
__global__ void k_wt(const float* __restrict__ w2) {
    int i = blockIdx.x * 256 + threadIdx.x;
    if (i < 64 * 800) {
        int co = i / 800, k = i % 800;
        g_W2T[k * 64 + co] = w2[i];
    }
}

// ---------------- kernel 1: conv1 + ternarize + BN + pool + ReLU ----------------
// one block per image; conv1 output (18432 floats) stays in smem
__global__ void __launch_bounds__(256) k_conv1(
    const float* __restrict__ x, const float* __restrict__ w,
    const float* __restrict__ bias, const float* __restrict__ bng,
    const float* __restrict__ bnb)
{
    extern __shared__ float sm[];
    float* sx  = sm;           // 784
    float* sw  = sm + 784;     // 800
    float* sb  = sw + 800;     // 32
    float* sc1 = sb + 32;      // 18432
    __shared__ float sscale[32], sbeta[32];

    int b = blockIdx.x, tid = threadIdx.x;
    const float* xb = x + b * 784;
    for (int i = tid; i < 784; i += 256) sx[i] = xb[i];
    for (int i = tid; i < 800; i += 256) sw[i] = w[i];
    if (tid < 32) {
        sb[tid]     = bias[tid];
        sscale[tid] = bng[tid] * BN_INV;
        sbeta[tid]  = bnb[tid];
    }
    __syncthreads();

    // conv1: 32ch x 24x24, packed pairs along x (9216 pair-units)
    float asum = 0.f;
    for (int u = tid; u < 9216; u += 256) {
        int c = u / 288, pp = u % 288;
        int oy = pp / 12, ox = (pp % 12) * 2;
        float bv = sb[c];
        ull acc = pk2(bv, bv);
        const float* wr = sw + c * 25;
        #pragma unroll
        for (int ky = 0; ky < 5; ky++) {
            const float* xr = sx + (oy + ky) * 28 + ox;
            #pragma unroll
            for (int kx = 0; kx < 5; kx++) {
                float wv = wr[ky * 5 + kx];
                fma2(acc, pk2(xr[kx], xr[kx + 1]), pk2(wv, wv));
            }
        }
        float lo, hi; unpk2(acc, lo, hi);
        int base = c * 576 + oy * 24 + ox;
        sc1[base] = lo; sc1[base + 1] = hi;
        asum += fabsf(lo) + fabsf(hi);
    }

    float tot = blockReduce<8>(asum);          // also fences sc1 writes
    float delta = 0.7f * tot / 18432.0f;

    float ms = 0.f, mc = 0.f;
    for (int u = tid; u < 18432; u += 256) {
        float a = fabsf(sc1[u]);
        if (a > delta) { ms += a; mc += 1.f; }
    }
    ms = blockReduce<8>(ms);
    mc = blockReduce<8>(mc);
    float alpha = ms / mc;

    // ternarize + BN + maxpool2 + ReLU -> [32,12,12]
    for (int u = tid; u < 4608; u += 256) {
        int c = u / 144, p = u % 144;
        int py = p / 12, px = p % 12;
        const float* q = sc1 + c * 576 + (2 * py) * 24 + 2 * px;
        float sc = sscale[c], bt = sbeta[c];
        float m = -CUDART_INF_F;
        float v;
        v = q[0];  m = fmaxf(m, fmaf(tern_val(v, delta, alpha), sc, bt));
        v = q[1];  m = fmaxf(m, fmaf(tern_val(v, delta, alpha), sc, bt));
        v = q[24]; m = fmaxf(m, fmaf(tern_val(v, delta, alpha), sc, bt));
        v = q[25]; m = fmaxf(m, fmaf(tern_val(v, delta, alpha), sc, bt));
        g_A1[b * 4608 + u] = fmaxf(m, 0.f);
    }
}

// ---------------- kernel 2: conv2 + ternarize + BN + pool + ReLU ----------------
// one block per image. 8 warps = 8 co-groups (8 out-channels each),
// 32 lanes = 32 position-pairs. per-k: 2 LDS + 2 uniform LDG.128 + 8 FFMA2.
__global__ void __launch_bounds__(256) k_conv2(
    const float* __restrict__ bias, const float* __restrict__ bng,
    const float* __restrict__ bnb)
{
    __shared__ float sin_[4608];
    __shared__ float sout[4096];
    __shared__ int   offs[800];
    __shared__ float sscale[64], sbeta[64], sb2[64];

    int b = blockIdx.x, tid = threadIdx.x;
    for (int i = tid; i < 4608; i += 256) sin_[i] = g_A1[b * 4608 + i];
    for (int k = tid; k < 800; k += 256) {
        int ci = k / 25, r = k % 25;
        offs[k] = ci * 144 + (r / 5) * 12 + (r % 5);
    }
    if (tid < 64) {
        sb2[tid]    = bias[tid];
        sscale[tid] = bng[tid] * BN_INV;
        sbeta[tid]  = bnb[tid];
    }
    __syncthreads();

    int w = tid >> 5, l = tid & 31;
    int p0 = 2 * l;
    int py = p0 >> 3, px = p0 & 7;
    int inbase = py * 12 + px;
    int cobase = w * 8;

    ull acc[8];
    #pragma unroll
    for (int j = 0; j < 8; j++) {
        float bv = sb2[cobase + j];
        acc[j] = pk2(bv, bv);
    }

    const float4* wt = ((const float4*)g_W2T) + w * 2;
    #pragma unroll 4
    for (int k = 0; k < 800; k++) {
        int o = inbase + offs[k];
        ull iv = pk2(sin_[o], sin_[o + 1]);
        float4 wa = wt[k * 16];
        float4 wb = wt[k * 16 + 1];
        fma2(acc[0], iv, pk2(wa.x, wa.x));
        fma2(acc[1], iv, pk2(wa.y, wa.y));
        fma2(acc[2], iv, pk2(wa.z, wa.z));
        fma2(acc[3], iv, pk2(wa.w, wa.w));
        fma2(acc[4], iv, pk2(wb.x, wb.x));
        fma2(acc[5], iv, pk2(wb.y, wb.y));
        fma2(acc[6], iv, pk2(wb.z, wb.z));
        fma2(acc[7], iv, pk2(wb.w, wb.w));
    }

    float asum = 0.f;
    #pragma unroll
    for (int j = 0; j < 8; j++) {
        float lo, hi; unpk2(acc[j], lo, hi);
        int co = cobase + j;
        sout[co * 64 + p0] = lo;
        sout[co * 64 + p0 + 1] = hi;
        asum += fabsf(lo) + fabsf(hi);
    }

    float tot = blockReduce<8>(asum);
    float delta = 0.7f * tot / 4096.0f;

    float ms = 0.f, mc = 0.f;
    #pragma unroll
    for (int j = 0; j < 8; j++) {
        float lo, hi; unpk2(acc[j], lo, hi);
        float a = fabsf(lo); if (a > delta) { ms += a; mc += 1.f; }
        a = fabsf(hi);       if (a > delta) { ms += a; mc += 1.f; }
    }
    ms = blockReduce<8>(ms);
    mc = blockReduce<8>(mc);
    float alpha = ms / mc;

    // ternarize + BN + maxpool2 + ReLU -> flattened [64*4*4]
    for (int u = tid; u < 1024; u += 256) {
        int c = u >> 4, p = u & 15;
        int py2 = p >> 2, px2 = p & 3;
        const float* q = sout + c * 64 + (2 * py2) * 8 + 2 * px2;
        float sc = sscale[c], bt = sbeta[c];
        float m = -CUDART_INF_F;
        float v;
        v = q[0]; m = fmaxf(m, fmaf(tern_val(v, delta, alpha), sc, bt));
        v = q[1]; m = fmaxf(m, fmaf(tern_val(v, delta, alpha), sc, bt));
        v = q[8]; m = fmaxf(m, fmaf(tern_val(v, delta, alpha), sc, bt));
        v = q[9]; m = fmaxf(m, fmaf(tern_val(v, delta, alpha), sc, bt));
        g_A2[b * 1024 + u] = fmaxf(m, 0.f);
    }
}

// ---------------- kernel 3: fc1 GEMM  F1 = A2 @ W1^T + b1 ----------------
#define FBM 64
#define FBN 64
#define FBK 32
__global__ void __launch_bounds__(256) k_fc1(
    const float* __restrict__ W, const float* __restrict__ bias)
{
    __shared__ __align__(16) float As[FBK][FBM + 4];
    __shared__ __align__(16) float Bs[FBK][FBN + 4];

    int bm = blockIdx.y * FBM, bn = blockIdx.x * FBN;
    int tid = threadIdx.x;
    int tx = tid & 15, ty = tid >> 4;

    ull acc[4][2];
    #pragma unroll
    for (int i = 0; i < 4; i++) { acc[i][0] = 0ull; acc[i][1] = 0ull; }

    for (int k0 = 0; k0 < 1024; k0 += FBK) {
        #pragma unroll
        for (int i = 0; i < 2; i++) {
            int f = tid * 2 + i;
            int row = f >> 3, kc = f & 7;
            float4 va = *(const float4*)(g_A2 + (bm + row) * 1024 + k0 + kc * 4);
            As[kc * 4 + 0][row] = va.x;
            As[kc * 4 + 1][row] = va.y;
            As[kc * 4 + 2][row] = va.z;
            As[kc * 4 + 3][row] = va.w;
            float4 vb = *(const float4*)(W + (bn + row) * 1024 + k0 + kc * 4);
            Bs[kc * 4 + 0][row] = vb.x;
            Bs[kc * 4 + 1][row] = vb.y;
            Bs[kc * 4 + 2][row] = vb.z;
            Bs[kc * 4 + 3][row] = vb.w;
        }
        __syncthreads();
        #pragma unroll
        for (int kk = 0; kk < FBK; kk++) {
            float4 a4 = *(const float4*)&As[kk][ty * 4];
            float4 b4 = *(const float4*)&Bs[kk][tx * 4];
            ull b01 = pk2(b4.x, b4.y), b23 = pk2(b4.z, b4.w);
            fma2(acc[0][0], pk2(a4.x, a4.x), b01); fma2(acc[0][1], pk2(a4.x, a4.x), b23);
            fma2(acc[1][0], pk2(a4.y, a4.y), b01); fma2(acc[1][1], pk2(a4.y, a4.y), b23);
            fma2(acc[2][0], pk2(a4.z, a4.z), b01); fma2(acc[2][1], pk2(a4.z, a4.z), b23);
            fma2(acc[3][0], pk2(a4.w, a4.w), b01); fma2(acc[3][1], pk2(a4.w, a4.w), b23);
        }
        __syncthreads();
    }

    float bl0 = bias[bn + tx * 4 + 0];
    float bl1 = bias[bn + tx * 4 + 1];
    float bl2 = bias[bn + tx * 4 + 2];
    float bl3 = bias[bn + tx * 4 + 3];
    #pragma unroll
    for (int i = 0; i < 4; i++) {
        int m = bm + ty * 4 + i;
        float lo, hi;
        unpk2(acc[i][0], lo, hi);
        g_F1[m * 512 + bn + tx * 4 + 0] = lo + bl0;
        g_F1[m * 512 + bn + tx * 4 + 1] = hi + bl1;
        unpk2(acc[i][1], lo, hi);
        g_F1[m * 512 + bn + tx * 4 + 2] = lo + bl2;
        g_F1[m * 512 + bn + tx * 4 + 3] = hi + bl3;
    }
}

// ---------------- kernel 4: per-row ternarize+ReLU -> fc2 -> ternarize ----------------
__global__ void __launch_bounds__(128) k_head(
    const float* __restrict__ W2, const float* __restrict__ b2,
    float* __restrict__ out)
{
    __shared__ float sh[512];
    __shared__ float so[10];

    int b = blockIdx.x, tid = threadIdx.x;
    float v[4];
    float asum = 0.f;
    #pragma unroll
    for (int i = 0; i < 4; i++) {
        v[i] = g_F1[b * 512 + tid + i * 128];
        asum += fabsf(v[i]);
    }
    float tot = blockReduce<4>(asum);
    float delta = 0.7f * tot / 512.0f;

    float ms = 0.f, mc = 0.f;
    #pragma unroll
    for (int i = 0; i < 4; i++) {
        float a = fabsf(v[i]);
        if (a > delta) { ms += a; mc += 1.f; }
    }
    ms = blockReduce<4>(ms);
    mc = blockReduce<4>(mc);
    float alpha = ms / mc;

    #pragma unroll
    for (int i = 0; i < 4; i++)
        sh[tid + i * 128] = (v[i] > delta) ? alpha : 0.f;   // relu(ternarize)
    __syncthreads();

    if (tid < 32) {
        for (int n = 0; n < 10; n++) {
            float s = 0.f;
            for (int j = tid; j < 512; j += 32)
                s += sh[j] * W2[n * 512 + j];
            #pragma unroll
            for (int o = 16; o > 0; o >>= 1) s += __shfl_xor_sync(0xFFFFFFFFu, s, o);
            if (tid == 0) so[n] = s + b2[n];
        }
    }
    __syncthreads();

    if (tid == 0) {
        float s = 0.f;
        #pragma unroll
        for (int n = 0; n < 10; n++) s += fabsf(so[n]);
        float d2 = 0.7f * s / 10.0f;
        float ms2 = 0.f, c2 = 0.f;
        #pragma unroll
        for (int n = 0; n < 10; n++) {
            float a = fabsf(so[n]);
            if (a > d2) { ms2 += a; c2 += 1.f; }
        }
        float a2 = ms2 / c2;
        #pragma unroll
        for (int n = 0; n < 10; n++)
            out[b * 10 + n] = tern_val(so[n], d2, a2);
    }
}

// ---------------- launch ----------------
extern "C" void kernel_launch(void* const* d_in, const int* in_sizes, int n_in,
                              void* d_out, int out_size)
{
    (void)in_sizes; (void)n_in; (void)out_size;
    const float* x       = (const float*)d_in[0];
    const float* conv1_w = (const float*)d_in[1];
    const float* conv1_b = (const float*)d_in[2];
    const float* bn1_g   = (const float*)d_in[3];
    const float* bn1_b   = (const float*)d_in[4];
    const float* conv2_w = (const float*)d_in[5];
    const float* conv2_b = (const float*)d_in[6];
    const float* bn2_g   = (const float*)d_in[7];
    const float* bn2_b   = (const float*)d_in[8];
    const float* fc1_w   = (const float*)d_in[9];
    const float* fc1_b   = (const float*)d_in[10];
    const float* fc2_w   = (const float*)d_in[11];
    const float* fc2_b   = (const float*)d_in[12];
    float* out = (float*)d_out;

    const int SMEM1 = (784 + 800 + 32 + 18432) * 4;   // 80192 B dynamic
    cudaFuncSetAttribute(k_conv1, cudaFuncAttributeMaxDynamicSharedMemorySize, SMEM1);

    k_wt<<<(64 * 800 + 255) / 256, 256>>>(conv2_w);
    k_conv1<<<2048, 256, SMEM1>>>(x, conv1_w, conv1_b, bn1_g, bn1_b);
    k_conv2<<<2048, 256>>>(conv2_b, bn2_g, bn2_b);
    k_fc1<<<dim3(512 / FBN, 2048 / FBM), 256>>>(fc1_w, fc1_b);
    k_head<<<2048, 128>>>(fc2_w, fc2_b, out);
}

// round 3
// speedup vs baseline: 1.9016x; 1.1672x over previous
#include <cuda_runtime.h>
#include <cuda_bf16.h>
#include <math_constants.h>

typedef unsigned long long ull;

// ---------------- f32x2 helpers ----------------
__device__ __forceinline__ ull pk2(float lo, float hi) {
    ull r; asm("mov.b64 %0, {%1, %2};" : "=l"(r) : "f"(lo), "f"(hi)); return r;
}
__device__ __forceinline__ ull dup2(float v) {
    ull r; asm("mov.b64 %0, {%1, %1};" : "=l"(r) : "f"(v)); return r;
}
__device__ __forceinline__ void unpk2(ull v, float& lo, float& hi) {
    asm("mov.b64 {%0, %1}, %2;" : "=f"(lo), "=f"(hi) : "l"(v));
}
__device__ __forceinline__ void fma2(ull& acc, ull a, ull b) {
    asm("fma.rn.f32x2 %0, %1, %2, %0;" : "+l"(acc) : "l"(a), "l"(b));
}
__device__ __forceinline__ void lds2(ull& a, ull& b, unsigned addr) {
    asm("ld.shared.v2.u64 {%0, %1}, [%2];" : "=l"(a), "=l"(b) : "r"(addr));
}
__device__ __forceinline__ float lds32(unsigned a) {
    float v; asm("ld.shared.f32 %0, [%1];" : "=f"(v) : "r"(a)); return v;
}
__device__ __forceinline__ void sts64(unsigned addr, ull v) {
    asm volatile("st.shared.b64 [%0], %1;" :: "r"(addr), "l"(v));
}
__device__ __forceinline__ void ldg2(ull& a, ull& b, const ull* p) {
    asm("ld.global.nc.v2.u64 {%0, %1}, [%2];" : "=l"(a), "=l"(b) : "l"(p));
}
__device__ __forceinline__ unsigned s2u(const void* p) {
    return (unsigned)__cvta_generic_to_shared(p);
}

// ---------------- scratch ----------------
__device__ __align__(16) float g_A1[2048 * 32 * 288];  // conv1 out, padded rows (stride 24)
__device__ __align__(16) float g_A2[2048 * 1024];
__device__ __align__(16) float g_F1[2048 * 512];
__device__ __align__(16) float g_W2T[800 * 64];        // conv2 weights [k][co]

#define BN_INV 0.9999950000374997f

template <int NW>
__device__ __forceinline__ float blockReduce(float v) {
    __shared__ float r[NW];
    #pragma unroll
    for (int o = 16; o > 0; o >>= 1) v += __shfl_xor_sync(0xFFFFFFFFu, v, o);
    int wid = threadIdx.x >> 5, lane = threadIdx.x & 31;
    __syncthreads();
    if (lane == 0) r[wid] = v;
    __syncthreads();
    float t = 0.f;
    #pragma unroll
    for (int i = 0; i < NW; i++) t += r[i];
    return t;
}

__device__ __forceinline__ float tern_val(float v, float delta, float alpha) {
    return (v > delta) ? alpha : ((v < -delta) ? -alpha : 0.f);
}

// ---------------- kernel 0: transpose conv2 weights ----------------
__global__ void k_wt(const float* __restrict__ w2) {
    int i = blockIdx.x * 256 + threadIdx.x;
    if (i < 64 * 800) {
        int co = i / 800, k = i % 800;
        g_W2T[k * 64 + co] = w2[i];
    }
}

// ================= conv1: weights in registers, rows via broadcast =================
// block=image, 256 thr = (c 0..31, rg 0..7); rg covers output rows rg*3..rg*3+2
#define SC1STR 578   // per-channel stride in sc1 (2-way store conflict only)
__global__ void __launch_bounds__(256, 2) k_conv1(
    const float* __restrict__ x, const float* __restrict__ w,
    const float* __restrict__ bias, const float* __restrict__ bng,
    const float* __restrict__ bnb)
{
    extern __shared__ float sm[];
    float* sx  = sm;            // 784
    float* sw  = sm + 784;      // 800
    float* sc1 = sm + 1584;     // 32*578
    __shared__ float sb[32], sscale[32], sbeta[32];

    int b = blockIdx.x, tid = threadIdx.x;
    const float* xb = x + b * 784;
    for (int i = tid; i < 784; i += 256) sx[i] = xb[i];
    for (int i = tid; i < 800; i += 256) sw[i] = w[i];
    if (tid < 32) {
        sb[tid]     = bias[tid];
        sscale[tid] = bng[tid] * BN_INV;
        sbeta[tid]  = bnb[tid];
    }
    __syncthreads();

    int c = tid & 31, rg = tid >> 5;
    float wr[25];
    #pragma unroll
    for (int i = 0; i < 25; i++) wr[i] = sw[c * 25 + i];
    float bv = sb[c];

    unsigned scb = s2u(sm) + (1584 + c * SC1STR) * 4;
    float asum = 0.f;

    #pragma unroll
    for (int rr = 0; rr < 3; rr++) {
        int r = rg * 3 + rr;
        ull acc[12];
        #pragma unroll
        for (int j = 0; j < 12; j++) acc[j] = dup2(bv);

        #pragma unroll
        for (int ky = 0; ky < 5; ky++) {
            const float4* xr4 = (const float4*)(sx + (r + ky) * 28);
            float v[28];
            #pragma unroll
            for (int q = 0; q < 7; q++) {
                float4 t = xr4[q];
                v[q*4] = t.x; v[q*4+1] = t.y; v[q*4+2] = t.z; v[q*4+3] = t.w;
            }
            #pragma unroll
            for (int kx = 0; kx < 5; kx++) {
                ull wd = dup2(wr[ky * 5 + kx]);
                #pragma unroll
                for (int j = 0; j < 12; j++)
                    fma2(acc[j], pk2(v[kx + 2*j], v[kx + 2*j + 1]), wd);
            }
        }
        unsigned ro = scb + r * 24 * 4;
        #pragma unroll
        for (int j = 0; j < 12; j++) {
            sts64(ro + j * 8, acc[j]);
            float lo, hi; unpk2(acc[j], lo, hi);
            asum += fabsf(lo) + fabsf(hi);
        }
    }

    float tot = blockReduce<8>(asum);
    float delta = 0.7f * tot / 18432.0f;

    // mask sums: re-read own 72 values
    float ms = 0.f, mc = 0.f;
    #pragma unroll
    for (int rr = 0; rr < 3; rr++) {
        int r = rg * 3 + rr;
        #pragma unroll
        for (int t = 0; t < 24; t++) {
            float a = fabsf(sc1[c * SC1STR + r * 24 + t]);
            if (a > delta) { ms += a; mc += 1.f; }
        }
    }
    ms = blockReduce<8>(ms);
    mc = blockReduce<8>(mc);
    float alpha = ms / mc;

    // tern + BN + pool + relu -> g_A1 padded [c][py(12)][24]
    for (int u = tid; u < 4608; u += 256) {
        int cc = u / 144, p = u % 144;
        int py = p / 12, px = p % 12;
        const float* q = sc1 + cc * SC1STR + (2 * py) * 24 + 2 * px;
        float sc = sscale[cc], bt = sbeta[cc];
        float m = -CUDART_INF_F, v;
        v = q[0];  m = fmaxf(m, fmaf(tern_val(v, delta, alpha), sc, bt));
        v = q[1];  m = fmaxf(m, fmaf(tern_val(v, delta, alpha), sc, bt));
        v = q[24]; m = fmaxf(m, fmaf(tern_val(v, delta, alpha), sc, bt));
        v = q[25]; m = fmaxf(m, fmaf(tern_val(v, delta, alpha), sc, bt));
        g_A1[b * 9216 + cc * 288 + py * 24 + px] = fmaxf(m, 0.f);
    }
}

// ================= conv2: co-pair accumulators, free weight pairs =================
// block=image, 256 thr: warp w = co-group (8 co), lane = position pair (p, p+32)
__global__ void __launch_bounds__(256) k_conv2(
    const float* __restrict__ bias, const float* __restrict__ bng,
    const float* __restrict__ bnb)
{
    extern __shared__ float sm[];
    float* sin_ = sm;           // 9216 (32 ci * 12 rows * stride 24)
    float* sout = sm + 9216;    // 4096
    __shared__ float sb2[64], sscale[64], sbeta[64];

    int b = blockIdx.x, tid = threadIdx.x;
    {
        const float4* src = (const float4*)(g_A1 + b * 9216);
        float4* dst = (float4*)sin_;
        for (int i = tid; i < 2304; i += 256) dst[i] = src[i];
    }
    if (tid < 64) {
        sb2[tid]    = bias[tid];
        sscale[tid] = bng[tid] * BN_INV;
        sbeta[tid]  = bnb[tid];
    }
    __syncthreads();

    int w = tid >> 5, lane = tid & 31;
    int py = lane >> 3, px = lane & 7;          // pos p = lane; second pos = lane+32

    ull acc[2][4];
    #pragma unroll
    for (int j = 0; j < 4; j++) {
        ull bvj = pk2(sb2[w * 8 + 2 * j], sb2[w * 8 + 2 * j + 1]);
        acc[0][j] = bvj; acc[1][j] = bvj;
    }

    unsigned a1 = s2u(sin_) + (py * 24 + px) * 4;
    unsigned a2 = s2u(sin_) + ((py + 4) * 24 + px) * 4;

    #pragma unroll 1
    for (int ci = 0; ci < 32; ci++) {
        const ull* wp = ((const ull*)g_W2T) + (ci * 25) * 32 + w * 4;
        #pragma unroll
        for (int t = 0; t < 25; t++) {
            int dy = t / 5, dx = t % 5;
            int io = (dy * 24 + dx) * 4;
            ull xd1 = dup2(lds32(a1 + io));
            ull xd2 = dup2(lds32(a2 + io));
            ull w01, w23, w45, w67;
            ldg2(w01, w23, wp + t * 32);
            ldg2(w45, w67, wp + t * 32 + 2);
            fma2(acc[0][0], xd1, w01); fma2(acc[0][1], xd1, w23);
            fma2(acc[0][2], xd1, w45); fma2(acc[0][3], xd1, w67);
            fma2(acc[1][0], xd2, w01); fma2(acc[1][1], xd2, w23);
            fma2(acc[1][2], xd2, w45); fma2(acc[1][3], xd2, w67);
        }
        a1 += 288 * 4; a2 += 288 * 4;
    }

    float asum = 0.f;
    #pragma unroll
    for (int pz = 0; pz < 2; pz++) {
        int p = lane + pz * 32;
        #pragma unroll
        for (int j = 0; j < 4; j++) {
            float lo, hi; unpk2(acc[pz][j], lo, hi);
            sout[(w * 8 + 2 * j) * 64 + p]     = lo;
            sout[(w * 8 + 2 * j + 1) * 64 + p] = hi;
            asum += fabsf(lo) + fabsf(hi);
        }
    }

    float tot = blockReduce<8>(asum);
    float delta = 0.7f * tot / 4096.0f;

    float ms = 0.f, mc = 0.f;
    #pragma unroll
    for (int pz = 0; pz < 2; pz++)
        #pragma unroll
        for (int j = 0; j < 4; j++) {
            float lo, hi; unpk2(acc[pz][j], lo, hi);
            float a = fabsf(lo); if (a > delta) { ms += a; mc += 1.f; }
            a = fabsf(hi);       if (a > delta) { ms += a; mc += 1.f; }
        }
    ms = blockReduce<8>(ms);
    mc = blockReduce<8>(mc);
    float alpha = ms / mc;

    for (int u = tid; u < 1024; u += 256) {
        int c = u >> 4, p = u & 15;
        int py2 = p >> 2, px2 = p & 3;
        const float* q = sout + c * 64 + (2 * py2) * 8 + 2 * px2;
        float sc = sscale[c], bt = sbeta[c];
        float m = -CUDART_INF_F, v;
        v = q[0]; m = fmaxf(m, fmaf(tern_val(v, delta, alpha), sc, bt));
        v = q[1]; m = fmaxf(m, fmaf(tern_val(v, delta, alpha), sc, bt));
        v = q[8]; m = fmaxf(m, fmaf(tern_val(v, delta, alpha), sc, bt));
        v = q[9]; m = fmaxf(m, fmaf(tern_val(v, delta, alpha), sc, bt));
        g_A2[b * 1024 + u] = fmaxf(m, 0.f);
    }
}

// ================= fc1: 32x64 tiles, 512 CTAs =================
__global__ void __launch_bounds__(256) k_fc1(
    const float* __restrict__ W, const float* __restrict__ bias)
{
    __shared__ __align__(16) float As[32][34];
    __shared__ __align__(16) float Bs[32][68];

    int bm = blockIdx.y * 32, bn = blockIdx.x * 64;
    int tid = threadIdx.x;
    int tx = tid & 15, ty = tid >> 4;

    ull acc[2][2] = {{0ull, 0ull}, {0ull, 0ull}};

    for (int k0 = 0; k0 < 1024; k0 += 32) {
        {
            int mr = tid >> 3, kc = tid & 7;
            float4 va = *(const float4*)(g_A2 + (bm + mr) * 1024 + k0 + kc * 4);
            As[kc*4+0][mr] = va.x; As[kc*4+1][mr] = va.y;
            As[kc*4+2][mr] = va.z; As[kc*4+3][mr] = va.w;
            #pragma unroll
            for (int i = 0; i < 2; i++) {
                int f = tid + i * 256;
                int nr = f >> 3, kc2 = f & 7;
                float4 vb = *(const float4*)(W + (bn + nr) * 1024 + k0 + kc2 * 4);
                Bs[kc2*4+0][nr] = vb.x; Bs[kc2*4+1][nr] = vb.y;
                Bs[kc2*4+2][nr] = vb.z; Bs[kc2*4+3][nr] = vb.w;
            }
        }
        __syncthreads();
        #pragma unroll
        for (int kk = 0; kk < 32; kk++) {
            float2 av = *(const float2*)&As[kk][ty * 2];
            ull b01, b23;
            lds2(b01, b23, s2u(&Bs[kk][tx * 4]));
            ull d0 = dup2(av.x), d1 = dup2(av.y);
            fma2(acc[0][0], d0, b01); fma2(acc[0][1], d0, b23);
            fma2(acc[1][0], d1, b01); fma2(acc[1][1], d1, b23);
        }
        __syncthreads();
    }

    float b0 = bias[bn + tx*4 + 0], b1 = bias[bn + tx*4 + 1];
    float b2 = bias[bn + tx*4 + 2], b3 = bias[bn + tx*4 + 3];
    #pragma unroll
    for (int i = 0; i < 2; i++) {
        int m = bm + ty * 2 + i;
        float lo, hi;
        unpk2(acc[i][0], lo, hi);
        g_F1[m * 512 + bn + tx*4 + 0] = lo + b0;
        g_F1[m * 512 + bn + tx*4 + 1] = hi + b1;
        unpk2(acc[i][1], lo, hi);
        g_F1[m * 512 + bn + tx*4 + 2] = lo + b2;
        g_F1[m * 512 + bn + tx*4 + 3] = hi + b3;
    }
}

// ================= head: tern+relu -> fc2 -> tern =================
__global__ void __launch_bounds__(128) k_head(
    const float* __restrict__ W2, const float* __restrict__ b2,
    float* __restrict__ out)
{
    __shared__ float sh[512];
    __shared__ float so[10];

    int b = blockIdx.x, tid = threadIdx.x;
    float4 v4 = ((const float4*)(g_F1 + b * 512))[tid];
    float asum = fabsf(v4.x) + fabsf(v4.y) + fabsf(v4.z) + fabsf(v4.w);
    float tot = blockReduce<4>(asum);
    float delta = 0.7f * tot / 512.0f;

    float ms = 0.f, mc = 0.f;
    float vv[4] = {v4.x, v4.y, v4.z, v4.w};
    #pragma unroll
    for (int i = 0; i < 4; i++) {
        float a = fabsf(vv[i]);
        if (a > delta) { ms += a; mc += 1.f; }
    }
    ms = blockReduce<4>(ms);
    mc = blockReduce<4>(mc);
    float alpha = ms / mc;

    #pragma unroll
    for (int i = 0; i < 4; i++)
        sh[tid * 4 + i] = (vv[i] > delta) ? alpha : 0.f;
    __syncthreads();

    int wd = tid >> 5, ln = tid & 31;
    for (int r = wd; r < 10; r += 4) {
        float s = 0.f;
        const float* wr = W2 + r * 512;
        for (int j = ln; j < 512; j += 32) s += sh[j] * wr[j];
        #pragma unroll
        for (int o = 16; o > 0; o >>= 1) s += __shfl_xor_sync(0xFFFFFFFFu, s, o);
        if (ln == 0) so[r] = s + b2[r];
    }
    __syncthreads();

    if (tid == 0) {
        float s = 0.f;
        #pragma unroll
        for (int n = 0; n < 10; n++) s += fabsf(so[n]);
        float d2 = 0.7f * s / 10.0f;
        float ms2 = 0.f, c2 = 0.f;
        #pragma unroll
        for (int n = 0; n < 10; n++) {
            float a = fabsf(so[n]);
            if (a > d2) { ms2 += a; c2 += 1.f; }
        }
        float a2 = ms2 / c2;
        #pragma unroll
        for (int n = 0; n < 10; n++)
            out[b * 10 + n] = tern_val(so[n], d2, a2);
    }
}

// ---------------- launch ----------------
extern "C" void kernel_launch(void* const* d_in, const int* in_sizes, int n_in,
                              void* d_out, int out_size)
{
    (void)in_sizes; (void)n_in; (void)out_size;
    const float* x       = (const float*)d_in[0];
    const float* conv1_w = (const float*)d_in[1];
    const float* conv1_b = (const float*)d_in[2];
    const float* bn1_g   = (const float*)d_in[3];
    const float* bn1_b   = (const float*)d_in[4];
    const float* conv2_w = (const float*)d_in[5];
    const float* conv2_b = (const float*)d_in[6];
    const float* bn2_g   = (const float*)d_in[7];
    const float* bn2_b   = (const float*)d_in[8];
    const float* fc1_w   = (const float*)d_in[9];
    const float* fc1_b   = (const float*)d_in[10];
    const float* fc2_w   = (const float*)d_in[11];
    const float* fc2_b   = (const float*)d_in[12];
    float* out = (float*)d_out;

    const int SMEM1 = (1584 + 32 * SC1STR) * 4;      // ~80.3 KB
    const int SMEM2 = (9216 + 4096) * 4;             // 53.25 KB
    static int configured = 0;
    cudaFuncSetAttribute(k_conv1, cudaFuncAttributeMaxDynamicSharedMemorySize, SMEM1);
    cudaFuncSetAttribute(k_conv2, cudaFuncAttributeMaxDynamicSharedMemorySize, SMEM2);
    (void)configured;

    k_wt<<<(64 * 800 + 255) / 256, 256>>>(conv2_w);
    k_conv1<<<2048, 256, SMEM1>>>(x, conv1_w, conv1_b, bn1_g, bn1_b);
    k_conv2<<<2048, 256, SMEM2>>>(conv2_b, bn2_g, bn2_b);
    k_fc1<<<dim3(8, 64), 256>>>(fc1_w, fc1_b);
    k_head<<<2048, 128>>>(fc2_w, fc2_b, out);
}

// round 4
// speedup vs baseline: 2.0939x; 1.1011x over previous
#include <cuda_runtime.h>
#include <cuda_bf16.h>
#include <math_constants.h>

typedef unsigned long long ull;

// ---------------- f32x2 helpers ----------------
__device__ __forceinline__ ull pk2(float lo, float hi) {
    ull r; asm("mov.b64 %0, {%1, %2};" : "=l"(r) : "f"(lo), "f"(hi)); return r;
}
__device__ __forceinline__ ull dup2(float v) {
    ull r; asm("mov.b64 %0, {%1, %1};" : "=l"(r) : "f"(v)); return r;
}
__device__ __forceinline__ void unpk2(ull v, float& lo, float& hi) {
    asm("mov.b64 {%0, %1}, %2;" : "=f"(lo), "=f"(hi) : "l"(v));
}
__device__ __forceinline__ void fma2(ull& acc, ull a, ull b) {
    asm("fma.rn.f32x2 %0, %1, %2, %0;" : "+l"(acc) : "l"(a), "l"(b));
}
__device__ __forceinline__ void lds2(ull& a, ull& b, unsigned addr) {
    asm("ld.shared.v2.u64 {%0, %1}, [%2];" : "=l"(a), "=l"(b) : "r"(addr));
}
__device__ __forceinline__ void lds128f(float& x, float& y, float& z, float& w, unsigned a) {
    asm("ld.shared.v4.f32 {%0, %1, %2, %3}, [%4];"
        : "=f"(x), "=f"(y), "=f"(z), "=f"(w) : "r"(a));
}
__device__ __forceinline__ float lds32(unsigned a) {
    float v; asm("ld.shared.f32 %0, [%1];" : "=f"(v) : "r"(a)); return v;
}
__device__ __forceinline__ void sts64(unsigned addr, ull v) {
    asm volatile("st.shared.b64 [%0], %1;" :: "r"(addr), "l"(v));
}
__device__ __forceinline__ void cpasync16(unsigned saddr, const void* g) {
    asm volatile("cp.async.ca.shared.global [%0], [%1], 16;" :: "r"(saddr), "l"(g));
}
#define CP_COMMIT()   asm volatile("cp.async.commit_group;")
#define CP_WAIT_ALL() asm volatile("cp.async.wait_group 0;")
__device__ __forceinline__ unsigned s2u(const void* p) {
    return (unsigned)__cvta_generic_to_shared(p);
}

// ---------------- scratch ----------------
__device__ __align__(16) float g_A1[2048 * 32 * 288];  // conv1 out [b][c][12 rows, stride 24]
__device__ __align__(16) float g_A2[1024 * 2048];      // conv2 out TRANSPOSED [feature k][image m]
__device__ __align__(16) float g_F1[2048 * 512];       // fc1 pre-ternarize [m][n]
__device__ __align__(16) float g_W2T[800 * 64];        // conv2 weights [k][co]
__device__ __align__(16) float g_W1T[1024 * 512];      // fc1 weights [k][n]

#define BN_INV 0.9999950000374997f

template <int NW>
__device__ __forceinline__ float blockReduce(float v) {
    __shared__ float r[NW];
    #pragma unroll
    for (int o = 16; o > 0; o >>= 1) v += __shfl_xor_sync(0xFFFFFFFFu, v, o);
    int wid = threadIdx.x >> 5, lane = threadIdx.x & 31;
    __syncthreads();
    if (lane == 0) r[wid] = v;
    __syncthreads();
    float t = 0.f;
    #pragma unroll
    for (int i = 0; i < NW; i++) t += r[i];
    return t;
}

__device__ __forceinline__ float tern_val(float v, float delta, float alpha) {
    return (v > delta) ? alpha : ((v < -delta) ? -alpha : 0.f);
}

// ---------------- k_pre: both weight transposes ----------------
#define N_W2 (64 * 800)
#define N_W1 (512 * 1024)
__global__ void k_pre(const float* __restrict__ w2, const float* __restrict__ w1) {
    int i = blockIdx.x * 256 + threadIdx.x;
    if (i < N_W2) {
        int co = i / 800, k = i % 800;
        g_W2T[k * 64 + co] = w2[i];
    } else if (i < N_W2 + N_W1) {
        int j = i - N_W2;
        int n = j / 1024, k = j % 1024;
        g_W1T[k * 512 + n] = w1[j];
    }
}

// ================= conv1 (unchanged structure) =================
#define SC1STR 578
__global__ void __launch_bounds__(256, 2) k_conv1(
    const float* __restrict__ x, const float* __restrict__ w,
    const float* __restrict__ bias, const float* __restrict__ bng,
    const float* __restrict__ bnb)
{
    extern __shared__ float sm[];
    float* sx  = sm;            // 784
    float* sw  = sm + 784;      // 800
    float* sc1 = sm + 1584;     // 32*578
    __shared__ float sb[32], sscale[32], sbeta[32];

    int b = blockIdx.x, tid = threadIdx.x;
    const float* xb = x + b * 784;
    for (int i = tid; i < 784; i += 256) sx[i] = xb[i];
    for (int i = tid; i < 800; i += 256) sw[i] = w[i];
    if (tid < 32) {
        sb[tid]     = bias[tid];
        sscale[tid] = bng[tid] * BN_INV;
        sbeta[tid]  = bnb[tid];
    }
    __syncthreads();

    int c = tid & 31, rg = tid >> 5;
    float wr[25];
    #pragma unroll
    for (int i = 0; i < 25; i++) wr[i] = sw[c * 25 + i];
    float bv = sb[c];

    unsigned scb = s2u(sm) + (1584 + c * SC1STR) * 4;
    float asum = 0.f;

    #pragma unroll
    for (int rr = 0; rr < 3; rr++) {
        int r = rg * 3 + rr;
        ull acc[12];
        #pragma unroll
        for (int j = 0; j < 12; j++) acc[j] = dup2(bv);

        #pragma unroll
        for (int ky = 0; ky < 5; ky++) {
            const float4* xr4 = (const float4*)(sx + (r + ky) * 28);
            float v[28];
            #pragma unroll
            for (int q = 0; q < 7; q++) {
                float4 t = xr4[q];
                v[q*4] = t.x; v[q*4+1] = t.y; v[q*4+2] = t.z; v[q*4+3] = t.w;
            }
            #pragma unroll
            for (int kx = 0; kx < 5; kx++) {
                ull wd = dup2(wr[ky * 5 + kx]);
                #pragma unroll
                for (int j = 0; j < 12; j++)
                    fma2(acc[j], pk2(v[kx + 2*j], v[kx + 2*j + 1]), wd);
            }
        }
        unsigned ro = scb + r * 24 * 4;
        #pragma unroll
        for (int j = 0; j < 12; j++) {
            sts64(ro + j * 8, acc[j]);
            float lo, hi; unpk2(acc[j], lo, hi);
            asum += fabsf(lo) + fabsf(hi);
        }
    }

    float tot = blockReduce<8>(asum);
    float delta = 0.7f * tot / 18432.0f;

    float ms = 0.f, mc = 0.f;
    #pragma unroll
    for (int rr = 0; rr < 3; rr++) {
        int r = rg * 3 + rr;
        #pragma unroll
        for (int t = 0; t < 24; t++) {
            float a = fabsf(sc1[c * SC1STR + r * 24 + t]);
            if (a > delta) { ms += a; mc += 1.f; }
        }
    }
    ms = blockReduce<8>(ms);
    mc = blockReduce<8>(mc);
    float alpha = ms / mc;

    for (int u = tid; u < 4608; u += 256) {
        int cc = u / 144, p = u % 144;
        int py = p / 12, px = p % 12;
        const float* q = sc1 + cc * SC1STR + (2 * py) * 24 + 2 * px;
        float sc = sscale[cc], bt = sbeta[cc];
        float m = -CUDART_INF_F, v;
        v = q[0];  m = fmaxf(m, fmaf(tern_val(v, delta, alpha), sc, bt));
        v = q[1];  m = fmaxf(m, fmaf(tern_val(v, delta, alpha), sc, bt));
        v = q[24]; m = fmaxf(m, fmaf(tern_val(v, delta, alpha), sc, bt));
        v = q[25]; m = fmaxf(m, fmaf(tern_val(v, delta, alpha), sc, bt));
        g_A1[b * 9216 + cc * 288 + py * 24 + px] = fmaxf(m, 0.f);
    }
}

// ================= conv2: 2 images/block, smem weights (cp.async dbuf) =================
// 256 thr: warp w = 8 out-channels (as 4 f32x2 pairs); lane = spatial pos (lane, lane+32)
// smem: sin[2*9216] | overlay{ swbuf[2][1600] , sout[2*4096] }
__global__ void __launch_bounds__(256, 2) k_conv2(
    const float* __restrict__ bias, const float* __restrict__ bng,
    const float* __restrict__ bnb)
{
    extern __shared__ float sm[];
    float* sin_ = sm;                 // 18432
    float* sov  = sm + 18432;         // 8192 overlay region
    __shared__ float sb2[64], sscale[64], sbeta[64];

    int b = blockIdx.x, tid = threadIdx.x;
    unsigned sin_u = s2u(sin_);
    unsigned sov_u = s2u(sov);

    // prologue: stage both images' input + ci=0 weights
    const float* gin = g_A1 + b * 18432;
    #pragma unroll
    for (int i = 0; i < 18; i++) {
        int o = tid + i * 256;                 // 0..4607
        cpasync16(sin_u + o * 16, gin + o * 4);
    }
    cpasync16(sov_u + tid * 16, g_W2T + tid * 4);
    if (tid < 144) cpasync16(sov_u + (tid + 256) * 16, g_W2T + (tid + 256) * 4);
    CP_COMMIT();

    if (tid < 64) {
        sb2[tid]    = bias[tid];
        sscale[tid] = bng[tid] * BN_INV;
        sbeta[tid]  = bnb[tid];
    }
    CP_WAIT_ALL();
    __syncthreads();

    int w = tid >> 5, lane = tid & 31;
    int py = lane >> 3, px = lane & 7;

    ull acc[2][2][4];
    #pragma unroll
    for (int j = 0; j < 4; j++) {
        ull bvj = pk2(sb2[w * 8 + 2 * j], sb2[w * 8 + 2 * j + 1]);
        acc[0][0][j] = bvj; acc[0][1][j] = bvj;
        acc[1][0][j] = bvj; acc[1][1][j] = bvj;
    }

    unsigned abase = sin_u + (py * 24 + px) * 4;
    unsigned wlane = w * 32;                      // w*8 floats = 32 bytes

    for (int ci = 0; ci < 32; ci++) {
        int cur = ci & 1;
        // prefetch next ci's weights into other buffer
        if (ci < 31) {
            const float* src = g_W2T + (ci + 1) * 1600;
            unsigned dst = sov_u + (cur ^ 1) * 6400;
            cpasync16(dst + tid * 16, src + tid * 4);
            if (tid < 144) cpasync16(dst + (tid + 256) * 16, src + (tid + 256) * 4);
            CP_COMMIT();
        }
        unsigned swc = sov_u + cur * 6400 + wlane;
        unsigned a0 = abase + ci * 1152;          // 288 floats per ci
        #pragma unroll
        for (int t = 0; t < 25; t++) {
            const int io = ((t / 5) * 24 + (t % 5)) * 4;
            float x00 = lds32(a0 + io);
            float x01 = lds32(a0 + io + 384);           // +4 rows
            float x10 = lds32(a0 + io + 36864);         // image 1
            float x11 = lds32(a0 + io + 36864 + 384);
            ull w01, w23, w45, w67;
            lds2(w01, w23, swc + t * 256);
            lds2(w45, w67, swc + t * 256 + 16);
            ull d;
            d = dup2(x00);
            fma2(acc[0][0][0], d, w01); fma2(acc[0][0][1], d, w23);
            fma2(acc[0][0][2], d, w45); fma2(acc[0][0][3], d, w67);
            d = dup2(x01);
            fma2(acc[0][1][0], d, w01); fma2(acc[0][1][1], d, w23);
            fma2(acc[0][1][2], d, w45); fma2(acc[0][1][3], d, w67);
            d = dup2(x10);
            fma2(acc[1][0][0], d, w01); fma2(acc[1][0][1], d, w23);
            fma2(acc[1][0][2], d, w45); fma2(acc[1][0][3], d, w67);
            d = dup2(x11);
            fma2(acc[1][1][0], d, w01); fma2(acc[1][1][1], d, w23);
            fma2(acc[1][1][2], d, w45); fma2(acc[1][1][3], d, w67);
        }
        if (ci < 31) { CP_WAIT_ALL(); __syncthreads(); }
    }

    // per-image ternarize stats from registers
    float as0 = 0.f, as1 = 0.f;
    #pragma unroll
    for (int pz = 0; pz < 2; pz++)
        #pragma unroll
        for (int j = 0; j < 4; j++) {
            float lo, hi;
            unpk2(acc[0][pz][j], lo, hi); as0 += fabsf(lo) + fabsf(hi);
            unpk2(acc[1][pz][j], lo, hi); as1 += fabsf(lo) + fabsf(hi);
        }
    float d0 = 0.7f * blockReduce<8>(as0) / 4096.0f;
    float d1 = 0.7f * blockReduce<8>(as1) / 4096.0f;

    float m0 = 0.f, c0 = 0.f, m1 = 0.f, c1 = 0.f;
    #pragma unroll
    for (int pz = 0; pz < 2; pz++)
        #pragma unroll
        for (int j = 0; j < 4; j++) {
            float lo, hi;
            unpk2(acc[0][pz][j], lo, hi);
            float a = fabsf(lo); if (a > d0) { m0 += a; c0 += 1.f; }
            a = fabsf(hi);       if (a > d0) { m0 += a; c0 += 1.f; }
            unpk2(acc[1][pz][j], lo, hi);
            a = fabsf(lo); if (a > d1) { m1 += a; c1 += 1.f; }
            a = fabsf(hi);       if (a > d1) { m1 += a; c1 += 1.f; }
        }
    m0 = blockReduce<8>(m0); c0 = blockReduce<8>(c0);
    m1 = blockReduce<8>(m1); c1 = blockReduce<8>(c1);
    float al0 = m0 / c0, al1 = m1 / c1;

    // write conv outputs to sout (safe: all warps passed reduction bars after last swbuf read)
    float* sout = sov;
    #pragma unroll
    for (int img = 0; img < 2; img++)
        #pragma unroll
        for (int pz = 0; pz < 2; pz++) {
            int p = lane + pz * 32;
            #pragma unroll
            for (int j = 0; j < 4; j++) {
                float lo, hi; unpk2(acc[img][pz][j], lo, hi);
                sout[img * 4096 + (w * 8 + 2 * j) * 64 + p]     = lo;
                sout[img * 4096 + (w * 8 + 2 * j + 1) * 64 + p] = hi;
            }
        }
    __syncthreads();

    // tern + BN + pool + relu -> g_A2 TRANSPOSED [feature][image]
    for (int u = tid; u < 2048; u += 256) {
        int img = u >> 10, idx = u & 1023;
        int c = idx >> 4, p = idx & 15;
        int py2 = p >> 2, px2 = p & 3;
        const float* q = sout + img * 4096 + c * 64 + (2 * py2) * 8 + 2 * px2;
        float delta = img ? d1 : d0;
        float alpha = img ? al1 : al0;
        float sc = sscale[c], bt = sbeta[c];
        float m = -CUDART_INF_F, v;
        v = q[0]; m = fmaxf(m, fmaf(tern_val(v, delta, alpha), sc, bt));
        v = q[1]; m = fmaxf(m, fmaf(tern_val(v, delta, alpha), sc, bt));
        v = q[8]; m = fmaxf(m, fmaf(tern_val(v, delta, alpha), sc, bt));
        v = q[9]; m = fmaxf(m, fmaf(tern_val(v, delta, alpha), sc, bt));
        g_A2[idx * 2048 + b * 2 + img] = fmaxf(m, 0.f);
    }
}

// ================= fc1: 128x64 tile, 8x4 micro-tile, cp.async dbuf =================
// grid (8, 16); 256 thr: tx=tid&15 -> 4 cols, ty=tid>>4 -> 8 rows
__global__ void __launch_bounds__(256) k_fc1(const float* __restrict__ bias)
{
    extern __shared__ float sm[];
    float* As = sm;              // [2][32][128]
    float* Bs = sm + 8192;       // [2][32][64]

    int bn = blockIdx.x * 64, bm = blockIdx.y * 128;
    int tid = threadIdx.x, tx = tid & 15, ty = tid >> 4;
    unsigned as_u = s2u(As), bs_u = s2u(Bs);

    ull acc[4][4];
    #pragma unroll
    for (int c = 0; c < 4; c++)
        #pragma unroll
        for (int r = 0; r < 4; r++) acc[c][r] = 0ull;

    // stage chunk 0
    #pragma unroll
    for (int i = 0; i < 4; i++) {
        int o = tid + i * 256;                 // 0..1023
        int kk = o >> 5, seg = o & 31;
        cpasync16(as_u + (kk * 128 + seg * 4) * 4, g_A2 + kk * 2048 + bm + seg * 4);
    }
    #pragma unroll
    for (int i = 0; i < 2; i++) {
        int o = tid + i * 256;                 // 0..511
        int kk = o >> 4, seg = o & 15;
        cpasync16(bs_u + (kk * 64 + seg * 4) * 4, g_W1T + kk * 512 + bn + seg * 4);
    }
    CP_COMMIT();
    CP_WAIT_ALL();
    __syncthreads();

    for (int kc = 0; kc < 32; kc++) {
        int cur = kc & 1;
        if (kc < 31) {
            int k0 = (kc + 1) * 32, nb = cur ^ 1;
            #pragma unroll
            for (int i = 0; i < 4; i++) {
                int o = tid + i * 256;
                int kk = o >> 5, seg = o & 31;
                cpasync16(as_u + (nb * 4096 + kk * 128 + seg * 4) * 4,
                          g_A2 + (k0 + kk) * 2048 + bm + seg * 4);
            }
            #pragma unroll
            for (int i = 0; i < 2; i++) {
                int o = tid + i * 256;
                int kk = o >> 4, seg = o & 15;
                cpasync16(bs_u + (nb * 2048 + kk * 64 + seg * 4) * 4,
                          g_W1T + (k0 + kk) * 512 + bn + seg * 4);
            }
            CP_COMMIT();
        }
        unsigned ab = as_u + cur * 16384 + ty * 32;     // ty*8 floats
        unsigned bb = bs_u + cur * 8192 + tx * 16;      // tx*4 floats
        #pragma unroll
        for (int kk = 0; kk < 32; kk++) {
            ull a01, a23, a45, a67;
            lds2(a01, a23, ab + kk * 512);
            lds2(a45, a67, ab + kk * 512 + 16);
            float b0, b1, b2, b3;
            lds128f(b0, b1, b2, b3, bb + kk * 256);
            ull d;
            d = dup2(b0);
            fma2(acc[0][0], a01, d); fma2(acc[0][1], a23, d);
            fma2(acc[0][2], a45, d); fma2(acc[0][3], a67, d);
            d = dup2(b1);
            fma2(acc[1][0], a01, d); fma2(acc[1][1], a23, d);
            fma2(acc[1][2], a45, d); fma2(acc[1][3], a67, d);
            d = dup2(b2);
            fma2(acc[2][0], a01, d); fma2(acc[2][1], a23, d);
            fma2(acc[2][2], a45, d); fma2(acc[2][3], a67, d);
            d = dup2(b3);
            fma2(acc[3][0], a01, d); fma2(acc[3][1], a23, d);
            fma2(acc[3][2], a45, d); fma2(acc[3][3], a67, d);
        }
        if (kc < 31) { CP_WAIT_ALL(); __syncthreads(); }
    }

    float bl[4];
    #pragma unroll
    for (int c = 0; c < 4; c++) bl[c] = bias[bn + tx * 4 + c];
    #pragma unroll
    for (int rp = 0; rp < 4; rp++) {
        int r0 = bm + ty * 8 + rp * 2;
        #pragma unroll
        for (int c = 0; c < 4; c++) {
            float lo, hi; unpk2(acc[c][rp], lo, hi);
            g_F1[r0 * 512 + bn + tx * 4 + c]       = lo + bl[c];
            g_F1[(r0 + 1) * 512 + bn + tx * 4 + c] = hi + bl[c];
        }
    }
}

// ================= head =================
__global__ void __launch_bounds__(128) k_head(
    const float* __restrict__ W2, const float* __restrict__ b2,
    float* __restrict__ out)
{
    __shared__ float sh[512];
    __shared__ float so[10];

    int b = blockIdx.x, tid = threadIdx.x;
    float4 v4 = ((const float4*)(g_F1 + b * 512))[tid];
    float asum = fabsf(v4.x) + fabsf(v4.y) + fabsf(v4.z) + fabsf(v4.w);
    float tot = blockReduce<4>(asum);
    float delta = 0.7f * tot / 512.0f;

    float ms = 0.f, mc = 0.f;
    float vv[4] = {v4.x, v4.y, v4.z, v4.w};
    #pragma unroll
    for (int i = 0; i < 4; i++) {
        float a = fabsf(vv[i]);
        if (a > delta) { ms += a; mc += 1.f; }
    }
    ms = blockReduce<4>(ms);
    mc = blockReduce<4>(mc);
    float alpha = ms / mc;

    #pragma unroll
    for (int i = 0; i < 4; i++)
        sh[tid * 4 + i] = (vv[i] > delta) ? alpha : 0.f;
    __syncthreads();

    int wd = tid >> 5, ln = tid & 31;
    for (int r = wd; r < 10; r += 4) {
        float s = 0.f;
        const float* wr = W2 + r * 512;
        for (int j = ln; j < 512; j += 32) s += sh[j] * wr[j];
        #pragma unroll
        for (int o = 16; o > 0; o >>= 1) s += __shfl_xor_sync(0xFFFFFFFFu, s, o);
        if (ln == 0) so[r] = s + b2[r];
    }
    __syncthreads();

    if (tid == 0) {
        float s = 0.f;
        #pragma unroll
        for (int n = 0; n < 10; n++) s += fabsf(so[n]);
        float d2 = 0.7f * s / 10.0f;
        float ms2 = 0.f, c2 = 0.f;
        #pragma unroll
        for (int n = 0; n < 10; n++) {
            float a = fabsf(so[n]);
            if (a > d2) { ms2 += a; c2 += 1.f; }
        }
        float a2 = ms2 / c2;
        #pragma unroll
        for (int n = 0; n < 10; n++)
            out[b * 10 + n] = tern_val(so[n], d2, a2);
    }
}

// ---------------- launch ----------------
extern "C" void kernel_launch(void* const* d_in, const int* in_sizes, int n_in,
                              void* d_out, int out_size)
{
    (void)in_sizes; (void)n_in; (void)out_size;
    const float* x       = (const float*)d_in[0];
    const float* conv1_w = (const float*)d_in[1];
    const float* conv1_b = (const float*)d_in[2];
    const float* bn1_g   = (const float*)d_in[3];
    const float* bn1_b   = (const float*)d_in[4];
    const float* conv2_w = (const float*)d_in[5];
    const float* conv2_b = (const float*)d_in[6];
    const float* bn2_g   = (const float*)d_in[7];
    const float* bn2_b   = (const float*)d_in[8];
    const float* fc1_w   = (const float*)d_in[9];
    const float* fc1_b   = (const float*)d_in[10];
    const float* fc2_w   = (const float*)d_in[11];
    const float* fc2_b   = (const float*)d_in[12];
    float* out = (float*)d_out;

    const int SMEM1 = (1584 + 32 * SC1STR) * 4;          // ~80.3 KB
    const int SMEM2 = (18432 + 8192) * 4;                // 106.5 KB
    const int SMEMF = (8192 + 4096) * 4;                 // 48 KB
    cudaFuncSetAttribute(k_conv1, cudaFuncAttributeMaxDynamicSharedMemorySize, SMEM1);
    cudaFuncSetAttribute(k_conv2, cudaFuncAttributeMaxDynamicSharedMemorySize, SMEM2);
    cudaFuncSetAttribute(k_fc1,   cudaFuncAttributeMaxDynamicSharedMemorySize, SMEMF);

    k_pre<<<(N_W2 + N_W1 + 255) / 256, 256>>>(conv2_w, fc1_w);
    k_conv1<<<2048, 256, SMEM1>>>(x, conv1_w, conv1_b, bn1_g, bn1_b);
    k_conv2<<<1024, 256, SMEM2>>>(conv2_b, bn2_g, bn2_b);
    k_fc1<<<dim3(8, 16), 256, SMEMF>>>(fc1_b);
    k_head<<<2048, 128>>>(fc2_w, fc2_b, out);
}

// round 5
// speedup vs baseline: 2.9171x; 1.3931x over previous
#include <cuda_runtime.h>
#include <cuda_bf16.h>
#include <math_constants.h>

typedef unsigned long long ull;

// ---------------- f32x2 helpers ----------------
__device__ __forceinline__ ull pk2(float lo, float hi) {
    ull r; asm("mov.b64 %0, {%1, %2};" : "=l"(r) : "f"(lo), "f"(hi)); return r;
}
__device__ __forceinline__ ull dup2(float v) {
    ull r; asm("mov.b64 %0, {%1, %1};" : "=l"(r) : "f"(v)); return r;
}
__device__ __forceinline__ void unpk2(ull v, float& lo, float& hi) {
    asm("mov.b64 {%0, %1}, %2;" : "=f"(lo), "=f"(hi) : "l"(v));
}
__device__ __forceinline__ void fma2(ull& acc, ull a, ull b) {
    asm("fma.rn.f32x2 %0, %1, %2, %0;" : "+l"(acc) : "l"(a), "l"(b));
}
__device__ __forceinline__ void lds2(ull& a, ull& b, unsigned addr) {
    asm("ld.shared.v2.u64 {%0, %1}, [%2];" : "=l"(a), "=l"(b) : "r"(addr));
}
__device__ __forceinline__ void lds128f(float& x, float& y, float& z, float& w, unsigned a) {
    asm("ld.shared.v4.f32 {%0, %1, %2, %3}, [%4];"
        : "=f"(x), "=f"(y), "=f"(z), "=f"(w) : "r"(a));
}
__device__ __forceinline__ float lds32(unsigned a) {
    float v; asm("ld.shared.f32 %0, [%1];" : "=f"(v) : "r"(a)); return v;
}
__device__ __forceinline__ void sts64(unsigned addr, ull v) {
    asm volatile("st.shared.b64 [%0], %1;" :: "r"(addr), "l"(v));
}
__device__ __forceinline__ void cpasync16(unsigned saddr, const void* g) {
    asm volatile("cp.async.ca.shared.global [%0], [%1], 16;" :: "r"(saddr), "l"(g));
}
#define CP_COMMIT()   asm volatile("cp.async.commit_group;")
#define CP_WAIT_ALL() asm volatile("cp.async.wait_group 0;")
__device__ __forceinline__ unsigned s2u(const void* p) {
    return (unsigned)__cvta_generic_to_shared(p);
}

// ---------------- scratch ----------------
__device__ __align__(16) float g_A1[2048 * 32 * 288];  // conv1 out [b][c][12 rows, stride 24]
__device__ __align__(16) float g_A2[1024 * 2048];      // conv2 out TRANSPOSED [feature k][image m]
__device__ __align__(16) float g_F1[2048 * 512];       // fc1 pre-ternarize [m][n]
__device__ __align__(16) float g_W2T[800 * 64];        // conv2 weights [k][co]
__device__ __align__(16) float g_W1T[1024 * 512];      // fc1 weights [k][n]

#define BN_INV 0.9999950000374997f

template <int NW>
__device__ __forceinline__ float blockReduce(float v) {
    __shared__ float r[NW];
    #pragma unroll
    for (int o = 16; o > 0; o >>= 1) v += __shfl_xor_sync(0xFFFFFFFFu, v, o);
    int wid = threadIdx.x >> 5, lane = threadIdx.x & 31;
    __syncthreads();
    if (lane == 0) r[wid] = v;
    __syncthreads();
    float t = 0.f;
    #pragma unroll
    for (int i = 0; i < NW; i++) t += r[i];
    return t;
}

__device__ __forceinline__ float tern_val(float v, float delta, float alpha) {
    return (v > delta) ? alpha : ((v < -delta) ? -alpha : 0.f);
}

// ---------------- k_pre: both weight transposes ----------------
#define N_W2 (64 * 800)
#define N_W1 (512 * 1024)
__global__ void k_pre(const float* __restrict__ w2, const float* __restrict__ w1) {
    int i = blockIdx.x * 256 + threadIdx.x;
    if (i < N_W2) {
        int co = i / 800, k = i % 800;
        g_W2T[k * 64 + co] = w2[i];
    } else if (i < N_W2 + N_W1) {
        int j = i - N_W2;
        int n = j / 1024, k = j % 1024;
        g_W1T[k * 512 + n] = w1[j];
    }
}

// ================= conv1 =================
#define SC1STR 578
__global__ void __launch_bounds__(256, 2) k_conv1(
    const float* __restrict__ x, const float* __restrict__ w,
    const float* __restrict__ bias, const float* __restrict__ bng,
    const float* __restrict__ bnb)
{
    extern __shared__ float sm[];
    float* sx  = sm;            // 784
    float* sw  = sm + 784;      // 800
    float* sc1 = sm + 1584;     // 32*578
    __shared__ float sb[32], sscale[32], sbeta[32];

    int b = blockIdx.x, tid = threadIdx.x;
    const float* xb = x + b * 784;
    for (int i = tid; i < 784; i += 256) sx[i] = xb[i];
    for (int i = tid; i < 800; i += 256) sw[i] = w[i];
    if (tid < 32) {
        sb[tid]     = bias[tid];
        sscale[tid] = bng[tid] * BN_INV;
        sbeta[tid]  = bnb[tid];
    }
    __syncthreads();

    int c = tid & 31, rg = tid >> 5;
    float wr[25];
    #pragma unroll
    for (int i = 0; i < 25; i++) wr[i] = sw[c * 25 + i];
    float bv = sb[c];

    unsigned scb = s2u(sm) + (1584 + c * SC1STR) * 4;
    float asum = 0.f;

    #pragma unroll
    for (int rr = 0; rr < 3; rr++) {
        int r = rg * 3 + rr;
        ull acc[12];
        #pragma unroll
        for (int j = 0; j < 12; j++) acc[j] = dup2(bv);

        #pragma unroll
        for (int ky = 0; ky < 5; ky++) {
            const float4* xr4 = (const float4*)(sx + (r + ky) * 28);
            float v[28];
            #pragma unroll
            for (int q = 0; q < 7; q++) {
                float4 t = xr4[q];
                v[q*4] = t.x; v[q*4+1] = t.y; v[q*4+2] = t.z; v[q*4+3] = t.w;
            }
            #pragma unroll
            for (int kx = 0; kx < 5; kx++) {
                ull wd = dup2(wr[ky * 5 + kx]);
                #pragma unroll
                for (int j = 0; j < 12; j++)
                    fma2(acc[j], pk2(v[kx + 2*j], v[kx + 2*j + 1]), wd);
            }
        }
        unsigned ro = scb + r * 24 * 4;
        #pragma unroll
        for (int j = 0; j < 12; j++) {
            sts64(ro + j * 8, acc[j]);
            float lo, hi; unpk2(acc[j], lo, hi);
            asum += fabsf(lo) + fabsf(hi);
        }
    }

    float tot = blockReduce<8>(asum);
    float delta = 0.7f * tot / 18432.0f;

    float ms = 0.f, mc = 0.f;
    #pragma unroll
    for (int rr = 0; rr < 3; rr++) {
        int r = rg * 3 + rr;
        #pragma unroll
        for (int t = 0; t < 24; t++) {
            float a = fabsf(sc1[c * SC1STR + r * 24 + t]);
            if (a > delta) { ms += a; mc += 1.f; }
        }
    }
    ms = blockReduce<8>(ms);
    mc = blockReduce<8>(mc);
    float alpha = ms / mc;

    for (int u = tid; u < 4608; u += 256) {
        int cc = u / 144, p = u % 144;
        int py = p / 12, px = p % 12;
        const float* q = sc1 + cc * SC1STR + (2 * py) * 24 + 2 * px;
        float sc = sscale[cc], bt = sbeta[cc];
        float m = -CUDART_INF_F, v;
        v = q[0];  m = fmaxf(m, fmaf(tern_val(v, delta, alpha), sc, bt));
        v = q[1];  m = fmaxf(m, fmaf(tern_val(v, delta, alpha), sc, bt));
        v = q[24]; m = fmaxf(m, fmaf(tern_val(v, delta, alpha), sc, bt));
        v = q[25]; m = fmaxf(m, fmaf(tern_val(v, delta, alpha), sc, bt));
        g_A1[b * 9216 + cc * 288 + py * 24 + px] = fmaxf(m, 0.f);
    }
}

// ================= conv2: 4 images/block =================
// 256 thr: warp w = 8 out-channels (4 f32x2 pairs); lane = pos (lane, lane+32) per image
// smem: sin[4*9216] | sov[16384]{ weights dbuf 2x1600 then sout 4x4096 }
__global__ void __launch_bounds__(256) k_conv2(
    const float* __restrict__ bias, const float* __restrict__ bng,
    const float* __restrict__ bnb)
{
    extern __shared__ float sm[];
    float* sin_ = sm;                 // 36864 floats
    float* sov  = sm + 36864;         // 16384 floats
    __shared__ float sb2[64], sscale[64], sbeta[64];

    int b = blockIdx.x, tid = threadIdx.x;
    unsigned sin_u = s2u(sin_);
    unsigned sov_u = s2u(sov);

    const float* gin = g_A1 + b * 4 * 9216;
    #pragma unroll
    for (int i = 0; i < 36; i++) {
        int o = tid + i * 256;                 // 0..9215
        cpasync16(sin_u + o * 16, gin + o * 4);
    }
    cpasync16(sov_u + tid * 16, g_W2T + tid * 4);
    if (tid < 144) cpasync16(sov_u + (tid + 256) * 16, g_W2T + (tid + 256) * 4);
    CP_COMMIT();

    if (tid < 64) {
        sb2[tid]    = bias[tid];
        sscale[tid] = bng[tid] * BN_INV;
        sbeta[tid]  = bnb[tid];
    }
    CP_WAIT_ALL();
    __syncthreads();

    int w = tid >> 5, lane = tid & 31;
    int py = lane >> 3, px = lane & 7;

    ull acc[4][2][4];
    #pragma unroll
    for (int j = 0; j < 4; j++) {
        ull bvj = pk2(sb2[w * 8 + 2 * j], sb2[w * 8 + 2 * j + 1]);
        #pragma unroll
        for (int img = 0; img < 4; img++) { acc[img][0][j] = bvj; acc[img][1][j] = bvj; }
    }

    unsigned abase = sin_u + (py * 24 + px) * 4;
    unsigned wlane = w * 32;

    for (int ci = 0; ci < 32; ci++) {
        int cur = ci & 1;
        if (ci < 31) {
            const float* src = g_W2T + (ci + 1) * 1600;
            unsigned dst = sov_u + (cur ^ 1) * 6400;
            cpasync16(dst + tid * 16, src + tid * 4);
            if (tid < 144) cpasync16(dst + (tid + 256) * 16, src + (tid + 256) * 4);
            CP_COMMIT();
        }
        unsigned swc = sov_u + cur * 6400 + wlane;
        unsigned a0 = abase + ci * 1152;
        #pragma unroll
        for (int t = 0; t < 25; t++) {
            const int io = ((t / 5) * 24 + (t % 5)) * 4;
            ull w01, w23, w45, w67;
            lds2(w01, w23, swc + t * 256);
            lds2(w45, w67, swc + t * 256 + 16);
            #pragma unroll
            for (int img = 0; img < 4; img++) {
                unsigned ai = a0 + img * 36864 + io;
                ull d0 = dup2(lds32(ai));
                ull d1 = dup2(lds32(ai + 384));
                fma2(acc[img][0][0], d0, w01); fma2(acc[img][0][1], d0, w23);
                fma2(acc[img][0][2], d0, w45); fma2(acc[img][0][3], d0, w67);
                fma2(acc[img][1][0], d1, w01); fma2(acc[img][1][1], d1, w23);
                fma2(acc[img][1][2], d1, w45); fma2(acc[img][1][3], d1, w67);
            }
        }
        if (ci < 31) { CP_WAIT_ALL(); __syncthreads(); }
    }

    // per-image stats
    float dlt[4], alf[4];
    #pragma unroll
    for (int img = 0; img < 4; img++) {
        float as = 0.f;
        #pragma unroll
        for (int pz = 0; pz < 2; pz++)
            #pragma unroll
            for (int j = 0; j < 4; j++) {
                float lo, hi; unpk2(acc[img][pz][j], lo, hi);
                as += fabsf(lo) + fabsf(hi);
            }
        dlt[img] = 0.7f * blockReduce<8>(as) / 4096.0f;
    }
    #pragma unroll
    for (int img = 0; img < 4; img++) {
        float ms = 0.f, mc = 0.f;
        #pragma unroll
        for (int pz = 0; pz < 2; pz++)
            #pragma unroll
            for (int j = 0; j < 4; j++) {
                float lo, hi; unpk2(acc[img][pz][j], lo, hi);
                float a = fabsf(lo); if (a > dlt[img]) { ms += a; mc += 1.f; }
                a = fabsf(hi);       if (a > dlt[img]) { ms += a; mc += 1.f; }
            }
        ms = blockReduce<8>(ms);
        mc = blockReduce<8>(mc);
        alf[img] = ms / mc;
    }

    // stage conv outputs (sov reuse; all warps past barriers => weight reads done)
    float* sout = sov;
    #pragma unroll
    for (int img = 0; img < 4; img++)
        #pragma unroll
        for (int pz = 0; pz < 2; pz++) {
            int p = lane + pz * 32;
            #pragma unroll
            for (int j = 0; j < 4; j++) {
                float lo, hi; unpk2(acc[img][pz][j], lo, hi);
                sout[img * 4096 + (w * 8 + 2 * j) * 64 + p]     = lo;
                sout[img * 4096 + (w * 8 + 2 * j + 1) * 64 + p] = hi;
            }
        }
    __syncthreads();

    // tern + BN + pool + relu -> g_A2 transposed [feature][image]
    for (int u = tid; u < 4096; u += 256) {
        int img = u >> 10, idx = u & 1023;
        int c = idx >> 4, p = idx & 15;
        int py2 = p >> 2, px2 = p & 3;
        const float* q = sout + img * 4096 + c * 64 + (2 * py2) * 8 + 2 * px2;
        float delta = dlt[img], alpha = alf[img];
        float sc = sscale[c], bt = sbeta[c];
        float m = -CUDART_INF_F, v;
        v = q[0]; m = fmaxf(m, fmaf(tern_val(v, delta, alpha), sc, bt));
        v = q[1]; m = fmaxf(m, fmaf(tern_val(v, delta, alpha), sc, bt));
        v = q[8]; m = fmaxf(m, fmaf(tern_val(v, delta, alpha), sc, bt));
        v = q[9]; m = fmaxf(m, fmaf(tern_val(v, delta, alpha), sc, bt));
        g_A2[idx * 2048 + b * 4 + img] = fmaxf(m, 0.f);
    }
}

// ================= fc1: 64x64 tile, 4x4 micro, grid 256 =================
__global__ void __launch_bounds__(256) k_fc1(const float* __restrict__ bias)
{
    extern __shared__ float sm[];
    float* As = sm;              // [2][32][64]
    float* Bs = sm + 4096;       // [2][32][64]

    int bn = blockIdx.x * 64, bm = blockIdx.y * 64;
    int tid = threadIdx.x, tx = tid & 15, ty = tid >> 4;
    unsigned as_u = s2u(As), bs_u = s2u(Bs);

    ull acc[4][2];
    #pragma unroll
    for (int c = 0; c < 4; c++) { acc[c][0] = 0ull; acc[c][1] = 0ull; }

    // stage chunk 0
    #pragma unroll
    for (int i = 0; i < 2; i++) {
        int o = tid + i * 256;                 // 0..511
        int kk = o >> 4, seg = o & 15;
        cpasync16(as_u + (kk * 64 + seg * 4) * 4, g_A2 + kk * 2048 + bm + seg * 4);
        cpasync16(bs_u + (kk * 64 + seg * 4) * 4, g_W1T + kk * 512 + bn + seg * 4);
    }
    CP_COMMIT();
    CP_WAIT_ALL();
    __syncthreads();

    for (int kc = 0; kc < 32; kc++) {
        int cur = kc & 1;
        if (kc < 31) {
            int k0 = (kc + 1) * 32, nb = cur ^ 1;
            #pragma unroll
            for (int i = 0; i < 2; i++) {
                int o = tid + i * 256;
                int kk = o >> 4, seg = o & 15;
                cpasync16(as_u + (nb * 2048 + kk * 64 + seg * 4) * 4,
                          g_A2 + (k0 + kk) * 2048 + bm + seg * 4);
                cpasync16(bs_u + (nb * 2048 + kk * 64 + seg * 4) * 4,
                          g_W1T + (k0 + kk) * 512 + bn + seg * 4);
            }
            CP_COMMIT();
        }
        unsigned ab = as_u + cur * 8192 + ty * 16;
        unsigned bb = bs_u + cur * 8192 + tx * 16;
        #pragma unroll
        for (int kk = 0; kk < 32; kk++) {
            ull a01, a23;
            lds2(a01, a23, ab + kk * 256);
            float b0, b1, b2, b3;
            lds128f(b0, b1, b2, b3, bb + kk * 256);
            ull d;
            d = dup2(b0); fma2(acc[0][0], a01, d); fma2(acc[0][1], a23, d);
            d = dup2(b1); fma2(acc[1][0], a01, d); fma2(acc[1][1], a23, d);
            d = dup2(b2); fma2(acc[2][0], a01, d); fma2(acc[2][1], a23, d);
            d = dup2(b3); fma2(acc[3][0], a01, d); fma2(acc[3][1], a23, d);
        }
        if (kc < 31) { CP_WAIT_ALL(); __syncthreads(); }
    }

    #pragma unroll
    for (int c = 0; c < 4; c++) {
        float bl = bias[bn + tx * 4 + c];
        int r0 = bm + ty * 4;
        float lo, hi;
        unpk2(acc[c][0], lo, hi);
        g_F1[r0 * 512 + bn + tx * 4 + c]       = lo + bl;
        g_F1[(r0 + 1) * 512 + bn + tx * 4 + c] = hi + bl;
        unpk2(acc[c][1], lo, hi);
        g_F1[(r0 + 2) * 512 + bn + tx * 4 + c] = lo + bl;
        g_F1[(r0 + 3) * 512 + bn + tx * 4 + c] = hi + bl;
    }
}

// ================= head =================
__global__ void __launch_bounds__(128) k_head(
    const float* __restrict__ W2, const float* __restrict__ b2,
    float* __restrict__ out)
{
    __shared__ float sh[512];
    __shared__ float so[10];

    int b = blockIdx.x, tid = threadIdx.x;
    float4 v4 = ((const float4*)(g_F1 + b * 512))[tid];
    float asum = fabsf(v4.x) + fabsf(v4.y) + fabsf(v4.z) + fabsf(v4.w);
    float tot = blockReduce<4>(asum);
    float delta = 0.7f * tot / 512.0f;

    float ms = 0.f, mc = 0.f;
    float vv[4] = {v4.x, v4.y, v4.z, v4.w};
    #pragma unroll
    for (int i = 0; i < 4; i++) {
        float a = fabsf(vv[i]);
        if (a > delta) { ms += a; mc += 1.f; }
    }
    ms = blockReduce<4>(ms);
    mc = blockReduce<4>(mc);
    float alpha = ms / mc;

    #pragma unroll
    for (int i = 0; i < 4; i++)
        sh[tid * 4 + i] = (vv[i] > delta) ? alpha : 0.f;
    __syncthreads();

    int wd = tid >> 5, ln = tid & 31;
    for (int r = wd; r < 10; r += 4) {
        float s = 0.f;
        const float* wr = W2 + r * 512;
        for (int j = ln; j < 512; j += 32) s += sh[j] * wr[j];
        #pragma unroll
        for (int o = 16; o > 0; o >>= 1) s += __shfl_xor_sync(0xFFFFFFFFu, s, o);
        if (ln == 0) so[r] = s + b2[r];
    }
    __syncthreads();

    if (tid == 0) {
        float s = 0.f;
        #pragma unroll
        for (int n = 0; n < 10; n++) s += fabsf(so[n]);
        float d2 = 0.7f * s / 10.0f;
        float ms2 = 0.f, c2 = 0.f;
        #pragma unroll
        for (int n = 0; n < 10; n++) {
            float a = fabsf(so[n]);
            if (a > d2) { ms2 += a; c2 += 1.f; }
        }
        float a2 = ms2 / c2;
        #pragma unroll
        for (int n = 0; n < 10; n++)
            out[b * 10 + n] = tern_val(so[n], d2, a2);
    }
}

// ---------------- launch ----------------
extern "C" void kernel_launch(void* const* d_in, const int* in_sizes, int n_in,
                              void* d_out, int out_size)
{
    (void)in_sizes; (void)n_in; (void)out_size;
    const float* x       = (const float*)d_in[0];
    const float* conv1_w = (const float*)d_in[1];
    const float* conv1_b = (const float*)d_in[2];
    const float* bn1_g   = (const float*)d_in[3];
    const float* bn1_b   = (const float*)d_in[4];
    const float* conv2_w = (const float*)d_in[5];
    const float* conv2_b = (const float*)d_in[6];
    const float* bn2_g   = (const float*)d_in[7];
    const float* bn2_b   = (const float*)d_in[8];
    const float* fc1_w   = (const float*)d_in[9];
    const float* fc1_b   = (const float*)d_in[10];
    const float* fc2_w   = (const float*)d_in[11];
    const float* fc2_b   = (const float*)d_in[12];
    float* out = (float*)d_out;

    const int SMEM1 = (1584 + 32 * SC1STR) * 4;          // ~80.3 KB
    const int SMEM2 = (36864 + 16384) * 4;               // 212992 B
    const int SMEMF = (4096 + 4096) * 4;                 // 32 KB
    cudaFuncSetAttribute(k_conv1, cudaFuncAttributeMaxDynamicSharedMemorySize, SMEM1);
    cudaFuncSetAttribute(k_conv2, cudaFuncAttributeMaxDynamicSharedMemorySize, SMEM2);
    cudaFuncSetAttribute(k_fc1,   cudaFuncAttributeMaxDynamicSharedMemorySize, SMEMF);

    k_pre<<<(N_W2 + N_W1 + 255) / 256, 256>>>(conv2_w, fc1_w);
    k_conv1<<<2048, 256, SMEM1>>>(x, conv1_w, conv1_b, bn1_g, bn1_b);
    k_conv2<<<512, 256, SMEM2>>>(conv2_b, bn2_g, bn2_b);
    k_fc1<<<dim3(8, 32), 256, SMEMF>>>(fc1_b);
    k_head<<<2048, 128>>>(fc2_w, fc2_b, out);
}